// round 2
// baseline (speedup 1.0000x reference)
#include <cuda_runtime.h>
#include <math.h>

#define NMAX 8192
#define TILE 2048
#define TPB  448       // 56 rows * 8 j-threads
#define RPC  56
#define GMAX 256

__device__ float2 g_part[GMAX];   // per-CTA (sum_logprob, count)

// ---- packed f32x2 helpers (sm_100+) ----------------------------------------
__device__ __forceinline__ float2 fma2(float2 a, float2 b, float2 c) {
    float2 d;
    asm("{\n\t.reg .b64 A,B,C,D;\n\t"
        "mov.b64 A,{%2,%3};\n\t"
        "mov.b64 B,{%4,%5};\n\t"
        "mov.b64 C,{%6,%7};\n\t"
        "fma.rn.f32x2 D,A,B,C;\n\t"
        "mov.b64 {%0,%1},D;\n\t}"
        : "=f"(d.x), "=f"(d.y)
        : "f"(a.x), "f"(a.y), "f"(b.x), "f"(b.y), "f"(c.x), "f"(c.y));
    return d;
}
__device__ __forceinline__ float2 add2(float2 a, float2 b) {
    float2 d;
    asm("{\n\t.reg .b64 A,B,D;\n\t"
        "mov.b64 A,{%2,%3};\n\t"
        "mov.b64 B,{%4,%5};\n\t"
        "add.rn.f32x2 D,A,B;\n\t"
        "mov.b64 {%0,%1},D;\n\t}"
        : "=f"(d.x), "=f"(d.y)
        : "f"(a.x), "f"(a.y), "f"(b.x), "f"(b.y));
    return d;
}
__device__ __forceinline__ float ex2a(float x) {
    float r; asm("ex2.approx.f32 %0, %1;" : "=f"(r) : "f"(x)); return r;
}

// ---------------- Main kernel: prep folded in, O(N^2) pass ------------------
__global__ void __launch_bounds__(TPB) pro_main(const float* __restrict__ pred,
                                                const float* __restrict__ ytg,
                                                int n, int padn)
{
    __shared__ __align__(16) float suz[TILE * 2];  // [u0,u1,z0,z1] groups of 2 j
    __shared__ __align__(16) float syt[TILE];
    __shared__ float sred[32];
    __shared__ float s_min;
    __shared__ float rlp[RPC], rct[RPC];

    const float K1    = 28.853900817779268f;   // (1/0.05) * log2(e)
    const float MAGIC = 12582912.0f;            // 1.5 * 2^23
    const float2 M2   = make_float2(MAGIC, MAGIC);
    const float2 NM2  = make_float2(-MAGIC, -MAGIC);
    const float2 N1   = make_float2(-1.0f, -1.0f);
    const float2 C5   = make_float2(0.0013333558f, 0.0013333558f);
    const float2 C4   = make_float2(0.0096181291f, 0.0096181291f);
    const float2 C3   = make_float2(0.0555041086f, 0.0555041086f);
    const float2 C2   = make_float2(0.2402265070f, 0.2402265070f);
    const float2 C1   = make_float2(0.6931471806f, 0.6931471806f);
    const float2 ONE  = make_float2(1.0f, 1.0f);

    int t  = threadIdx.x;
    int tx = t & 7;
    int ty = t >> 3;
    int k  = blockIdx.x * RPC + ty;

    float ytk, ypk;
    if (k < n) { ytk = ytg[k]; ypk = pred[k] * 20.0f; }
    else       { ytk = -1e30f; ypk = 0.0f; }
    float  ytke = ytk - 1e-8f;
    float2 yk2  = make_float2(ytk, ytk);

    float mn = 1e30f;
    float s0 = 0, s1 = 0, s2 = 0, s3 = 0, s4 = 0, s5 = 0, s6 = 0, s7 = 0;

    for (int base = 0; base < padn; base += TILE) {
        __syncthreads();
        for (int i = t; i < TILE; i += TPB) {
            int gi = base + i;
            float y, u;
            if (gi < n) { y = ytg[gi]; u = pred[gi] * K1; mn = fminf(mn, y); }
            else        { y = 1e30f;   u = 0.0f; }
            int g = i >> 1, o = i & 1;
            suz[g * 4 + o]     = u;
            suz[g * 4 + 2 + o] = -u * y;
            syt[i] = y;
        }
        __syncthreads();

        const float4* suz4 = (const float4*)suz;
        const float4* syt4 = (const float4*)syt;

        #pragma unroll 2
        for (int jb = tx * 8; jb < TILE; jb += 64) {
            int g = jb >> 1;
            float4 a  = suz4[g + 0];        // u(j0),u(j1),z(j0),z(j1)
            float4 b  = suz4[g + 1];        // j2,j3
            float4 c  = suz4[g + 2];        // j4,j5
            float4 d4 = suz4[g + 3];        // j6,j7
            float4 ya = syt4[jb >> 2];       // yt j0..j3
            float4 yb = syt4[(jb >> 2) + 1]; // yt j4..j7

            // ---- slots j0,j1 via packed-FMA exp2 polynomial ----
            float2 tt0 = fma2(yk2, make_float2(a.x, a.y), make_float2(a.z, a.w));
            float2 r0  = add2(tt0, M2);
            float2 rm  = add2(r0, NM2);              // round(tt0), exact
            float2 f   = fma2(rm, N1, tt0);          // frac in [-0.5, 0.5]
            float2 p   = fma2(f, C5, C4);
            p = fma2(f, p, C3);
            p = fma2(f, p, C2);
            p = fma2(f, p, C1);
            p = fma2(f, p, ONE);
            float ev0 = __int_as_float(__float_as_int(p.x) + (__float_as_int(r0.x) << 23));
            float ev1 = __int_as_float(__float_as_int(p.y) + (__float_as_int(r0.y) << 23));

            // ---- slots j2..j7 via MUFU ex2 ----
            float2 tt1 = fma2(yk2, make_float2(b.x, b.y),  make_float2(b.z, b.w));
            float2 tt2 = fma2(yk2, make_float2(c.x, c.y),  make_float2(c.z, c.w));
            float2 tt3 = fma2(yk2, make_float2(d4.x, d4.y), make_float2(d4.z, d4.w));
            float ev2 = ex2a(tt1.x), ev3 = ex2a(tt1.y);
            float ev4 = ex2a(tt2.x), ev5 = ex2a(tt2.y);
            float ev6 = ex2a(tt3.x), ev7 = ex2a(tt3.y);

            if (ya.x < ytke) s0 += ev0;
            if (ya.y < ytke) s1 += ev1;
            if (ya.z < ytke) s2 += ev2;
            if (ya.w < ytke) s3 += ev3;
            if (yb.x < ytke) s4 += ev4;
            if (yb.y < ytke) s5 += ev5;
            if (yb.z < ytke) s6 += ev6;
            if (yb.w < ytke) s7 += ev7;
        }
    }

    // ---- global min (every CTA streamed the full array) ----
    #pragma unroll
    for (int o = 16; o; o >>= 1) mn = fminf(mn, __shfl_xor_sync(0xffffffffu, mn, o));
    if ((t & 31) == 0) sred[t >> 5] = mn;
    __syncthreads();
    if (t < 32) {
        float v = (t < (TPB >> 5)) ? sred[t] : 1e30f;
        #pragma unroll
        for (int o = 16; o; o >>= 1) v = fminf(v, __shfl_xor_sync(0xffffffffu, v, o));
        if (t == 0) s_min = v;
    }
    __syncthreads();
    float ytmin = s_min;

    // ---- per-row reduce across the 8 j-threads ----
    float s = ((s0 + s1) + (s2 + s3)) + ((s4 + s5) + (s6 + s7));
    s += __shfl_xor_sync(0xffffffffu, s, 1);
    s += __shfl_xor_sync(0xffffffffu, s, 2);
    s += __shfl_xor_sync(0xffffffffu, s, 4);

    if (tx == 0) {
        float lpr = 0.0f, cc = 0.0f;
        if (k < n) {
            float d = ytk - ytmin;
            if (d > 1e-8f) {
                float lp = ypk * d;
                lpr = lp - logf(expf(lp) + s);
                cc  = 1.0f;
            }
        }
        rlp[ty] = lpr; rct[ty] = cc;
    }
    __syncthreads();
    if (t == 0) {   // deterministic fixed-order per-CTA reduce
        float tot = 0.0f, c = 0.0f;
        #pragma unroll
        for (int i = 0; i < RPC; i++) { tot += rlp[i]; c += rct[i]; }
        g_part[blockIdx.x] = make_float2(tot, c);
    }
}

// ---------------- Finish: reduce CTA partials ------------------------------
__global__ void __launch_bounds__(256) pro_finish(float* out, int g)
{
    __shared__ float st[32], sc[32];
    int t = threadIdx.x;
    float tot = 0.0f, cnt = 0.0f;
    for (int i = t; i < g; i += 256) {
        float2 p = g_part[i];
        tot += p.x; cnt += p.y;
    }
    #pragma unroll
    for (int o = 16; o; o >>= 1) {
        tot += __shfl_xor_sync(0xffffffffu, tot, o);
        cnt += __shfl_xor_sync(0xffffffffu, cnt, o);
    }
    if ((t & 31) == 0) { st[t >> 5] = tot; sc[t >> 5] = cnt; }
    __syncthreads();
    if (t < 32) {
        float a = (t < 8) ? st[t] : 0.0f;
        float b = (t < 8) ? sc[t] : 0.0f;
        #pragma unroll
        for (int o = 4; o; o >>= 1) {
            a += __shfl_xor_sync(0xffffffffu, a, o);
            b += __shfl_xor_sync(0xffffffffu, b, o);
        }
        if (t == 0) out[0] = (b > 0.0f) ? (-a / b) : 0.0f;
    }
}

// ---------------- Launch -----------------------------------------------------
extern "C" void kernel_launch(void* const* d_in, const int* in_sizes, int n_in,
                              void* d_out, int out_size)
{
    const float* pred = (const float*)d_in[0];   // predict_similarity
    const float* yt   = (const float*)d_in[1];   // true_similarity
    int n = in_sizes[0];
    if (n > NMAX) n = NMAX;
    int padn = ((n + TILE - 1) / TILE) * TILE;

    int grid = (n + RPC - 1) / RPC;              // 147 CTAs for n=8192
    if (grid > GMAX) grid = GMAX;

    pro_main<<<grid, TPB>>>(pred, yt, n, padn);
    pro_finish<<<1, 256>>>((float*)d_out, grid);
}

// round 5
// speedup vs baseline: 2.6308x; 2.6308x over previous
#include <cuda_runtime.h>
#include <math.h>

#define NMAX 8192
#define TILE 2048
#define TPB  256      // 8 j-lanes x 32 row-pair slots
#define RPC  64       // rows per CTA (32 slots x 2 rows)
#define GMAX 128

__device__ float2 g_part[GMAX];   // per-CTA (sum_logprob, count)

__device__ __forceinline__ float ex2a(float x) {
    float r; asm("ex2.approx.f32 %0, %1;" : "=f"(r) : "f"(x)); return r;
}

// ---------------- Main kernel: O(N^2) pass, prep + min folded in ------------
__global__ void __launch_bounds__(TPB) pro_main(const float* __restrict__ pred,
                                                const float* __restrict__ ytg,
                                                int n, int padn)
{
    __shared__ __align__(16) float su[TILE];   // u_j  = yp_j * (20*log2e)
    __shared__ __align__(16) float sz[TILE];   // z_j  = -u_j * yt_j
    __shared__ __align__(16) float sy[TILE];   // yt_j
    __shared__ float sred[8];
    __shared__ float s_min;
    __shared__ float rlp[RPC], rct[RPC];

    const float K1  = 28.853900817779268f;     // (1/0.05) * log2(e)
    const float EPS = 1e-8f;

    int t  = threadIdx.x;
    int tx = t & 7;
    int ty = t >> 3;
    int k0 = blockIdx.x * RPC + ty * 2;
    int k1 = k0 + 1;

    float yt0 = (k0 < n) ? ytg[k0] : -1e30f;
    float yt1 = (k1 < n) ? ytg[k1] : -1e30f;
    float yp0 = (k0 < n) ? pred[k0] * 20.0f : 0.0f;
    float yp1 = (k1 < n) ? pred[k1] * 20.0f : 0.0f;
    float e0 = yt0 - EPS;                       // predicate thresholds
    float e1 = yt1 - EPS;

    float a0 = 0.0f, a1 = 0.0f;   // row0 accumulators
    float b0 = 0.0f, b1 = 0.0f;   // row1 accumulators
    float mn = 1e30f;

    for (int base = 0; base < padn; base += TILE) {
        __syncthreads();
        for (int i = t; i < TILE; i += TPB) {
            int gi = base + i;
            float y, u;
            if (gi < n) { y = ytg[gi]; u = pred[gi] * K1; mn = fminf(mn, y); }
            else        { y = 1e30f;   u = 0.0f; }
            su[i] = u; sz[i] = -u * y; sy[i] = y;
        }
        __syncthreads();

        const float4* su4 = (const float4*)su;
        const float4* sz4 = (const float4*)sz;
        const float4* sy4 = (const float4*)sy;

        #pragma unroll 2
        for (int i = tx; i < TILE / 4; i += 8) {
            float4 u4 = su4[i];
            float4 z4 = sz4[i];
            float4 y4 = sy4[i];

            // row 0: arg = u*(yt0 - ytj) = fma(yt0, u, z)
            float v00 = ex2a(fmaf(yt0, u4.x, z4.x));
            float v01 = ex2a(fmaf(yt0, u4.y, z4.y));
            float v02 = ex2a(fmaf(yt0, u4.z, z4.z));
            float v03 = ex2a(fmaf(yt0, u4.w, z4.w));
            if (y4.x < e0) a0 += v00;
            if (y4.y < e0) a1 += v01;
            if (y4.z < e0) a0 += v02;
            if (y4.w < e0) a1 += v03;

            // row 1 (reuses the same smem values)
            float v10 = ex2a(fmaf(yt1, u4.x, z4.x));
            float v11 = ex2a(fmaf(yt1, u4.y, z4.y));
            float v12 = ex2a(fmaf(yt1, u4.z, z4.z));
            float v13 = ex2a(fmaf(yt1, u4.w, z4.w));
            if (y4.x < e1) b0 += v10;
            if (y4.y < e1) b1 += v11;
            if (y4.z < e1) b0 += v12;
            if (y4.w < e1) b1 += v13;
        }
    }

    // ---- block-wide global min (each CTA streamed the whole array) ----
    #pragma unroll
    for (int o = 16; o; o >>= 1) mn = fminf(mn, __shfl_xor_sync(0xffffffffu, mn, o));
    if ((t & 31) == 0) sred[t >> 5] = mn;
    __syncthreads();
    if (t < 8) {
        float v = sred[t];
        #pragma unroll
        for (int o = 4; o; o >>= 1) v = fminf(v, __shfl_xor_sync(0xffu, v, o));  // mask = active lanes!
        if (t == 0) s_min = v;
    }
    __syncthreads();
    float ytmin = s_min;

    // ---- reduce the 8 j-lanes per row (all lanes participate) ----
    float s0 = a0 + a1;
    float s1 = b0 + b1;
    #pragma unroll
    for (int o = 1; o < 8; o <<= 1) {
        s0 += __shfl_xor_sync(0xffffffffu, s0, o);
        s1 += __shfl_xor_sync(0xffffffffu, s1, o);
    }

    if (tx == 0) {
        float lp0 = 0.0f, c0 = 0.0f, lp1 = 0.0f, c1 = 0.0f;
        if (k0 < n) {
            float d = yt0 - ytmin;
            if (d > EPS) { float lp = yp0 * d; lp0 = lp - logf(expf(lp) + s0); c0 = 1.0f; }
        }
        if (k1 < n) {
            float d = yt1 - ytmin;
            if (d > EPS) { float lp = yp1 * d; lp1 = lp - logf(expf(lp) + s1); c1 = 1.0f; }
        }
        rlp[ty * 2]     = lp0;  rct[ty * 2]     = c0;
        rlp[ty * 2 + 1] = lp1;  rct[ty * 2 + 1] = c1;
    }
    __syncthreads();
    if (t == 0) {   // deterministic fixed-order per-CTA reduce
        float tot = 0.0f, c = 0.0f;
        #pragma unroll
        for (int i = 0; i < RPC; i++) { tot += rlp[i]; c += rct[i]; }
        g_part[blockIdx.x] = make_float2(tot, c);
    }
}

// ---------------- Finish: reduce CTA partials ------------------------------
__global__ void __launch_bounds__(128) pro_finish(float* out, int g)
{
    __shared__ float st[4], sc[4];
    int t = threadIdx.x;
    float tot = 0.0f, cnt = 0.0f;
    if (t < g) { float2 p = g_part[t]; tot = p.x; cnt = p.y; }
    #pragma unroll
    for (int o = 16; o; o >>= 1) {       // executed by ALL threads (full warps)
        tot += __shfl_xor_sync(0xffffffffu, tot, o);
        cnt += __shfl_xor_sync(0xffffffffu, cnt, o);
    }
    if ((t & 31) == 0) { st[t >> 5] = tot; sc[t >> 5] = cnt; }
    __syncthreads();
    if (t == 0) {
        float a = st[0] + st[1] + st[2] + st[3];
        float b = sc[0] + sc[1] + sc[2] + sc[3];
        out[0] = (b > 0.0f) ? (-a / b) : 0.0f;
    }
}

// ---------------- Launch -----------------------------------------------------
extern "C" void kernel_launch(void* const* d_in, const int* in_sizes, int n_in,
                              void* d_out, int out_size)
{
    const float* pred = (const float*)d_in[0];   // predict_similarity
    const float* yt   = (const float*)d_in[1];   // true_similarity
    int n = in_sizes[0];
    if (n > NMAX) n = NMAX;
    int padn = ((n + TILE - 1) / TILE) * TILE;
    int grid = (n + RPC - 1) / RPC;              // 128 for n=8192
    if (grid > GMAX) grid = GMAX;

    pro_main<<<grid, TPB>>>(pred, yt, n, padn);
    pro_finish<<<1, 128>>>((float*)d_out, grid);
}